// round 10
// baseline (speedup 1.0000x reference)
#include <cuda_runtime.h>
#include <cuda_fp16.h>

// SimpleGRU: B=2048, T=2048, H=32, scalar input.
// One warp = FOUR batch elements as two packed half2 streams ({A,B},{C,D});
// 512 single-warp blocks -> <=1 warp per SMSP: the warp owns the fma pipe
// (HFMA2 rt2 exclusive), and the two independent streams hide each other's
// LDS/MUFU latency. Weights duplicated {w,w}, shared by both streams.
// h broadcast: interleaved smem {a_j,b_j}; 1 STS.64 + 1 syncwarp + 16 LDS.128.
// Matvec: 2 chains/gate/stream (depth 16). Sigmoid via tanh.approx.f16x2.

#define FULL_MASK 0xffffffffu

__device__ __forceinline__ __half2 htanh2(__half2 a) {
    unsigned int d, s = *reinterpret_cast<unsigned int*>(&a);
    asm("tanh.approx.f16x2 %0, %1;" : "=r"(d) : "r"(s));
    return *reinterpret_cast<__half2*>(&d);
}
__device__ __forceinline__ __half2 u2h(unsigned int u) {
    return *reinterpret_cast<const __half2*>(&u);
}
__device__ __forceinline__ unsigned int h2u(__half2 h) {
    return *reinterpret_cast<unsigned int*>(&h);
}

__global__ void __launch_bounds__(32, 1)
gru_kernel(const float* __restrict__ x,
           const float* __restrict__ w_ih,
           const float* __restrict__ w_hh,
           const float* __restrict__ b_ih,
           const float* __restrict__ b_hh,
           const float* __restrict__ head_w,
           const float* __restrict__ head_b,
           float* __restrict__ out,
           int B, int T)
{
    const int b0 = blockIdx.x * 4;          // four batch elements per warp
    const int i  = threadIdx.x;             // lane == hidden unit, H == 32

    // [parity][2*j + s]: s=0 -> stream1 {hA_j,hB_j}, s=1 -> stream2 {hC_j,hD_j}
    __shared__ __align__(16) unsigned int hsh[2][64];

    // Duplicated {w,w} W_hh rows for unit i; r,z prescaled by 0.5.
    __half2 wr[32], wz[32], wn[32];
    {
        const float* Wr = w_hh + (0  + i) * 32;
        const float* Wz = w_hh + (32 + i) * 32;
        const float* Wn = w_hh + (64 + i) * 32;
        #pragma unroll
        for (int j = 0; j < 32; j++) {
            wr[j] = __float2half2_rn(Wr[j] * 0.5f);
            wz[j] = __float2half2_rn(Wz[j] * 0.5f);
            wn[j] = __float2half2_rn(Wn[j]);
        }
    }

    const __half2 wir2 = __float2half2_rn(w_ih[i]      * 0.5f);
    const __half2 cr2  = __float2half2_rn((b_ih[i]      + b_hh[i])      * 0.5f);
    const __half2 wiz2 = __float2half2_rn(w_ih[32 + i] * 0.5f);
    const __half2 cz2  = __float2half2_rn((b_ih[32 + i] + b_hh[32 + i]) * 0.5f);
    const __half2 win2 = __float2half2_rn(w_ih[64 + i]);
    const __half2 cnx2 = __float2half2_rn(b_ih[64 + i]);
    const __half2 cnh2 = __float2half2_rn(b_hh[64 + i]);
    const __half2 hlf2 = __float2half2_rn(0.5f);
    const __half2 zero = __float2half2_rn(0.0f);

    __half2 h2a = zero;                     // {hA_i, hB_i}
    __half2 h2b = zero;                     // {hC_i, hD_i}
    const float* xA = x + (long long)b0 * T;
    const float* xB = xA + T;
    const float* xC = xB + T;
    const float* xD = xC + T;

    for (int t0 = 0; t0 < T; t0 += 32) {
        unsigned int xpa = h2u(__floats2half2_rn(xA[t0 + i], xB[t0 + i]));
        unsigned int xpb = h2u(__floats2half2_rn(xC[t0 + i], xD[t0 + i]));
        #pragma unroll 2
        for (int k = 0; k < 32; k++) {
            __half2 xta = u2h(__shfl_sync(FULL_MASK, xpa, k));
            __half2 xtb = u2h(__shfl_sync(FULL_MASK, xpb, k));
            const int p = k & 1;            // buffer parity

            // One STS.64: both streams' packed h for this unit, interleaved.
            *reinterpret_cast<uint2*>(&hsh[p][2 * i]) = make_uint2(h2u(h2a), h2u(h2b));
            __syncwarp();                   // visible; WAR safe via parity

            // Chains: 2 per gate per stream (depth 16). x-side folded into
            // chain0 of r/z; n chain0 init = h-side bias.
            __half2 rA0 = __hfma2(xta, wir2, cr2), rA1 = zero;
            __half2 zA0 = __hfma2(xta, wiz2, cz2), zA1 = zero;
            __half2 nA0 = cnh2,                    nA1 = zero;
            __half2 rB0 = __hfma2(xtb, wir2, cr2), rB1 = zero;
            __half2 zB0 = __hfma2(xtb, wiz2, cz2), zB1 = zero;
            __half2 nB0 = cnh2,                    nB1 = zero;

            const uint4* hp = (const uint4*)&hsh[p][0];
            #pragma unroll
            for (int jj = 0; jj < 16; jj++) {
                uint4 q = hp[jj];           // {a_{2jj}, b_{2jj}, a_{2jj+1}, b_{2jj+1}}
                __half2 a0 = u2h(q.x), b0 = u2h(q.y);
                __half2 a1 = u2h(q.z), b1 = u2h(q.w);
                rA0 = __hfma2(wr[2*jj],   a0, rA0);
                rA1 = __hfma2(wr[2*jj+1], a1, rA1);
                zA0 = __hfma2(wz[2*jj],   a0, zA0);
                zA1 = __hfma2(wz[2*jj+1], a1, zA1);
                nA0 = __hfma2(wn[2*jj],   a0, nA0);
                nA1 = __hfma2(wn[2*jj+1], a1, nA1);
                rB0 = __hfma2(wr[2*jj],   b0, rB0);
                rB1 = __hfma2(wr[2*jj+1], b1, rB1);
                zB0 = __hfma2(wz[2*jj],   b0, zB0);
                zB1 = __hfma2(wz[2*jj+1], b1, zB1);
                nB0 = __hfma2(wn[2*jj],   b0, nB0);
                nB1 = __hfma2(wn[2*jj+1], b1, nB1);
            }

            // ---- stream 1 tail ----
            {
                __half2 pre_r = __hadd2(rA0, rA1);
                __half2 pre_z = __hadd2(zA0, zA1);
                __half2 hn2   = __hadd2(nA0, nA1);
                __half2 rg = __hfma2(htanh2(pre_r), hlf2, hlf2);
                __half2 zg = __hfma2(htanh2(pre_z), hlf2, hlf2);
                __half2 narg = __hfma2(rg, hn2, __hfma2(xta, win2, cnx2));
                __half2 ng = htanh2(narg);
                h2a = __hfma2(zg, __hsub2(h2a, ng), ng);
            }
            // ---- stream 2 tail ----
            {
                __half2 pre_r = __hadd2(rB0, rB1);
                __half2 pre_z = __hadd2(zB0, zB1);
                __half2 hn2   = __hadd2(nB0, nB1);
                __half2 rg = __hfma2(htanh2(pre_r), hlf2, hlf2);
                __half2 zg = __hfma2(htanh2(pre_z), hlf2, hlf2);
                __half2 narg = __hfma2(rg, hn2, __hfma2(xtb, win2, cnx2));
                __half2 ng = htanh2(narg);
                h2b = __hfma2(zg, __hsub2(h2b, ng), ng);
            }
        }
    }

    // Head: out[b][o] = sum_i h_i * head_w[o][i] + head_b[o]  (fp32)
    float2 fa = __half22float2(h2a);
    float2 fb = __half22float2(h2b);
    float w0 = head_w[i], w1 = head_w[32 + i];
    float p[8] = { fa.x * w0, fa.x * w1, fa.y * w0, fa.y * w1,
                   fb.x * w0, fb.x * w1, fb.y * w0, fb.y * w1 };
    #pragma unroll
    for (int m = 16; m > 0; m >>= 1) {
        #pragma unroll
        for (int q = 0; q < 8; q++)
            p[q] += __shfl_xor_sync(FULL_MASK, p[q], m);
    }
    if (i == 0) {
        #pragma unroll
        for (int q = 0; q < 8; q++)
            out[2 * b0 + q] = p[q] + head_b[q & 1];
    }
}

extern "C" void kernel_launch(void* const* d_in, const int* in_sizes, int n_in,
                              void* d_out, int out_size) {
    const float* x      = (const float*)d_in[0];
    const float* w_ih   = (const float*)d_in[1];
    const float* w_hh   = (const float*)d_in[2];
    const float* b_ih   = (const float*)d_in[3];
    const float* b_hh   = (const float*)d_in[4];
    const float* head_w = (const float*)d_in[5];
    const float* head_b = (const float*)d_in[6];
    float* out = (float*)d_out;

    const int B = out_size / 2;           // 2048
    const int T = in_sizes[0] / B;        // 2048

    gru_kernel<<<B / 4, 32>>>(x, w_ih, w_hh, b_ih, b_hh, head_w, head_b, out, B, T);
}

// round 11
// speedup vs baseline: 1.0582x; 1.0582x over previous
#include <cuda_runtime.h>
#include <cuda_fp16.h>

// SimpleGRU: B=2048, T=2048, H=32, scalar input.
// One warp = two batch elements; lane i = hidden unit i of both.
// Interleaved-batch packing: state h2 = {hA_i, hB_i} half2; weights {w,w}.
// R11: no __syncwarp in the step loop — warp is fully convergent (zero
// divergent branches), STS->LDS through in-order MIO is warp-visible;
// parity double-buffer removes the WAR hazard. Compiler fence only.
// Matvec: 2 chains/gate, depth 16 (hadd tree 9->3). x-side folded into
// r/z chain-0 inits. Sigmoid via tanh.approx.f16x2.

#define FULL_MASK 0xffffffffu

__device__ __forceinline__ __half2 htanh2(__half2 a) {
    unsigned int d, s = *reinterpret_cast<unsigned int*>(&a);
    asm("tanh.approx.f16x2 %0, %1;" : "=r"(d) : "r"(s));
    return *reinterpret_cast<__half2*>(&d);
}
__device__ __forceinline__ __half2 u2h(unsigned int u) {
    return *reinterpret_cast<const __half2*>(&u);
}
__device__ __forceinline__ unsigned int h2u(__half2 h) {
    return *reinterpret_cast<unsigned int*>(&h);
}

__global__ void __launch_bounds__(32, 1)
gru_kernel(const float* __restrict__ x,
           const float* __restrict__ w_ih,
           const float* __restrict__ w_hh,
           const float* __restrict__ b_ih,
           const float* __restrict__ b_hh,
           const float* __restrict__ head_w,
           const float* __restrict__ head_b,
           float* __restrict__ out,
           int B, int T)
{
    const int b0 = blockIdx.x * 2;          // two batch elements per warp
    const int i  = threadIdx.x;             // lane == hidden unit, H == 32

    // [parity][unit j] -> packed {hA_j, hB_j}
    __shared__ __align__(16) unsigned int hsh[2][32];

    // Duplicated {w,w} W_hh rows for unit i; r,z prescaled by 0.5.
    __half2 wr[32], wz[32], wn[32];
    {
        const float* Wr = w_hh + (0  + i) * 32;
        const float* Wz = w_hh + (32 + i) * 32;
        const float* Wn = w_hh + (64 + i) * 32;
        #pragma unroll
        for (int j = 0; j < 32; j++) {
            wr[j] = __float2half2_rn(Wr[j] * 0.5f);
            wz[j] = __float2half2_rn(Wz[j] * 0.5f);
            wn[j] = __float2half2_rn(Wn[j]);
        }
    }

    const __half2 wir2 = __float2half2_rn(w_ih[i]      * 0.5f);
    const __half2 cr2  = __float2half2_rn((b_ih[i]      + b_hh[i])      * 0.5f);
    const __half2 wiz2 = __float2half2_rn(w_ih[32 + i] * 0.5f);
    const __half2 cz2  = __float2half2_rn((b_ih[32 + i] + b_hh[32 + i]) * 0.5f);
    const __half2 win2 = __float2half2_rn(w_ih[64 + i]);
    const __half2 cnx2 = __float2half2_rn(b_ih[64 + i]);
    const __half2 cnh2 = __float2half2_rn(b_hh[64 + i]);
    const __half2 hlf2 = __float2half2_rn(0.5f);
    const __half2 zero = __float2half2_rn(0.0f);

    __half2 h2 = zero;                      // packed state {hA_i, hB_i}
    const float* xA = x + (long long)b0 * T;
    const float* xB = xA + T;

    for (int t0 = 0; t0 < T; t0 += 32) {
        unsigned int xp = h2u(__floats2half2_rn(xA[t0 + i], xB[t0 + i]));
        #pragma unroll 4
        for (int k = 0; k < 32; k++) {
            __half2 xt2 = u2h(__shfl_sync(FULL_MASK, xp, k));
            const int p = k & 1;            // buffer parity

            hsh[p][i] = h2u(h2);            // one raw STS.32
            asm volatile("" ::: "memory");  // compiler fence only; warp is
                                            // convergent, MIO is in-order,
                                            // parity buffer kills WAR

            // 8x LDS.128 broadcast: all 32 packed h pairs.
            const uint4* hp = (const uint4*)&hsh[p][0];
            uint4 q0 = hp[0], q1 = hp[1], q2 = hp[2], q3 = hp[3];
            uint4 q4 = hp[4], q5 = hp[5], q6 = hp[6], q7 = hp[7];
            unsigned int H[32] = {q0.x,q0.y,q0.z,q0.w, q1.x,q1.y,q1.z,q1.w,
                                  q2.x,q2.y,q2.z,q2.w, q3.x,q3.y,q3.z,q3.w,
                                  q4.x,q4.y,q4.z,q4.w, q5.x,q5.y,q5.z,q5.w,
                                  q6.x,q6.y,q6.z,q6.w, q7.x,q7.y,q7.z,q7.w};

            // Matvec: 2 chains per gate, depth 16.
            // r/z chain0 init = folded x-side; n chain0 init = h-side bias.
            __half2 r0 = __hfma2(xt2, wir2, cr2), r1 = zero;
            __half2 z0 = __hfma2(xt2, wiz2, cz2), z1 = zero;
            __half2 n0 = cnh2,                    n1 = zero;
            #pragma unroll
            for (int j = 0; j < 32; j += 2) {
                __half2 g0 = u2h(H[j]), g1 = u2h(H[j + 1]);
                r0 = __hfma2(wr[j],     g0, r0);
                r1 = __hfma2(wr[j + 1], g1, r1);
                z0 = __hfma2(wz[j],     g0, z0);
                z1 = __hfma2(wz[j + 1], g1, z1);
                n0 = __hfma2(wn[j],     g0, n0);
                n1 = __hfma2(wn[j + 1], g1, n1);
            }
            __half2 pre_r = __hadd2(r0, r1);
            __half2 pre_z = __hadd2(z0, z1);
            __half2 hn2   = __hadd2(n0, n1);

            // Packed gate math over {A, B}.
            __half2 rg = __hfma2(htanh2(pre_r), hlf2, hlf2);   // sigmoid
            __half2 zg = __hfma2(htanh2(pre_z), hlf2, hlf2);
            __half2 narg = __hfma2(rg, hn2, __hfma2(xt2, win2, cnx2));
            __half2 ng = htanh2(narg);

            h2 = __hfma2(zg, __hsub2(h2, ng), ng);   // (1-z)*n + z*h, packed
        }
    }

    // Head: out[b][o] = sum_i h_i * head_w[o][i] + head_b[o]  (fp32)
    float2 hf = __half22float2(h2);
    float ha = hf.x, hb = hf.y;
    float p0a = ha * head_w[i], p1a = ha * head_w[32 + i];
    float p0b = hb * head_w[i], p1b = hb * head_w[32 + i];
    #pragma unroll
    for (int m = 16; m > 0; m >>= 1) {
        p0a += __shfl_xor_sync(FULL_MASK, p0a, m);
        p1a += __shfl_xor_sync(FULL_MASK, p1a, m);
        p0b += __shfl_xor_sync(FULL_MASK, p0b, m);
        p1b += __shfl_xor_sync(FULL_MASK, p1b, m);
    }
    if (i == 0) {
        out[2 * b0]     = p0a + head_b[0];
        out[2 * b0 + 1] = p1a + head_b[1];
        out[2 * b0 + 2] = p0b + head_b[0];
        out[2 * b0 + 3] = p1b + head_b[1];
    }
}

extern "C" void kernel_launch(void* const* d_in, const int* in_sizes, int n_in,
                              void* d_out, int out_size) {
    const float* x      = (const float*)d_in[0];
    const float* w_ih   = (const float*)d_in[1];
    const float* w_hh   = (const float*)d_in[2];
    const float* b_ih   = (const float*)d_in[3];
    const float* b_hh   = (const float*)d_in[4];
    const float* head_w = (const float*)d_in[5];
    const float* head_b = (const float*)d_in[6];
    float* out = (float*)d_out;

    const int B = out_size / 2;           // 2048
    const int T = in_sizes[0] / B;        // 2048

    gru_kernel<<<B / 2, 32>>>(x, w_ih, w_hh, b_ih, b_hh, head_w, head_b, out, B, T);
}

// round 12
// speedup vs baseline: 1.0635x; 1.0051x over previous
#include <cuda_runtime.h>
#include <cuda_fp16.h>

// SimpleGRU: B=2048, T=2048, H=32, scalar input.
// One warp = two batch elements; lane i = hidden unit i of both.
// Interleaved-batch packing: state h2 = {hA_i, hB_i} half2; weights {w,w}.
// R12: r,z as single depth-32 chains issued FIRST (tanh_r/tanh_z retire
// under the n-chain); n as 2 chains depth 16; manual 2-step parity unroll
// (static smem addrs, no syncwarp - warp convergent, parity kills WAR).
// Sigmoid via tanh.approx.f16x2. x-side folded into r/z chain inits.

#define FULL_MASK 0xffffffffu

__device__ __forceinline__ __half2 htanh2(__half2 a) {
    unsigned int d, s = *reinterpret_cast<unsigned int*>(&a);
    asm("tanh.approx.f16x2 %0, %1;" : "=r"(d) : "r"(s));
    return *reinterpret_cast<__half2*>(&d);
}
__device__ __forceinline__ __half2 u2h(unsigned int u) {
    return *reinterpret_cast<const __half2*>(&u);
}
__device__ __forceinline__ unsigned int h2u(__half2 h) {
    return *reinterpret_cast<unsigned int*>(&h);
}

__global__ void __launch_bounds__(32, 1)
gru_kernel(const float* __restrict__ x,
           const float* __restrict__ w_ih,
           const float* __restrict__ w_hh,
           const float* __restrict__ b_ih,
           const float* __restrict__ b_hh,
           const float* __restrict__ head_w,
           const float* __restrict__ head_b,
           float* __restrict__ out,
           int B, int T)
{
    const int b0 = blockIdx.x * 2;          // two batch elements per warp
    const int i  = threadIdx.x;             // lane == hidden unit, H == 32

    // [parity][unit j] -> packed {hA_j, hB_j}
    __shared__ __align__(16) unsigned int hsh[2][32];

    // Duplicated {w,w} W_hh rows for unit i; r,z prescaled by 0.5.
    __half2 wr[32], wz[32], wn[32];
    {
        const float* Wr = w_hh + (0  + i) * 32;
        const float* Wz = w_hh + (32 + i) * 32;
        const float* Wn = w_hh + (64 + i) * 32;
        #pragma unroll
        for (int j = 0; j < 32; j++) {
            wr[j] = __float2half2_rn(Wr[j] * 0.5f);
            wz[j] = __float2half2_rn(Wz[j] * 0.5f);
            wn[j] = __float2half2_rn(Wn[j]);
        }
    }

    const __half2 wir2 = __float2half2_rn(w_ih[i]      * 0.5f);
    const __half2 cr2  = __float2half2_rn((b_ih[i]      + b_hh[i])      * 0.5f);
    const __half2 wiz2 = __float2half2_rn(w_ih[32 + i] * 0.5f);
    const __half2 cz2  = __float2half2_rn((b_ih[32 + i] + b_hh[32 + i]) * 0.5f);
    const __half2 win2 = __float2half2_rn(w_ih[64 + i]);
    const __half2 cnx2 = __float2half2_rn(b_ih[64 + i]);
    const __half2 cnh2 = __float2half2_rn(b_hh[64 + i]);
    const __half2 hlf2 = __float2half2_rn(0.5f);
    const __half2 zero = __float2half2_rn(0.0f);

    __half2 h2 = zero;                      // packed state {hA_i, hB_i}
    const float* xA = x + (long long)b0 * T;
    const float* xB = xA + T;

    for (int t0 = 0; t0 < T; t0 += 32) {
        unsigned int xp = h2u(__floats2half2_rn(xA[t0 + i], xB[t0 + i]));
        #pragma unroll 2
        for (int kk = 0; kk < 16; kk++) {
            #pragma unroll
            for (int p = 0; p < 2; p++) {   // manual parity unroll, static addrs
                const int k = 2 * kk + p;
                __half2 xt2 = u2h(__shfl_sync(FULL_MASK, xp, k));

                hsh[p][i] = h2u(h2);            // one raw STS.32
                asm volatile("" ::: "memory");  // compiler fence only

                // 8x LDS.128 broadcast: all 32 packed h pairs.
                const uint4* hp = (const uint4*)&hsh[p][0];
                uint4 q0 = hp[0], q1 = hp[1], q2 = hp[2], q3 = hp[3];
                uint4 q4 = hp[4], q5 = hp[5], q6 = hp[6], q7 = hp[7];
                unsigned int H[32] = {q0.x,q0.y,q0.z,q0.w, q1.x,q1.y,q1.z,q1.w,
                                      q2.x,q2.y,q2.z,q2.w, q3.x,q3.y,q3.z,q3.w,
                                      q4.x,q4.y,q4.z,q4.w, q5.x,q5.y,q5.z,q5.w,
                                      q6.x,q6.y,q6.z,q6.w, q7.x,q7.y,q7.z,q7.w};

                // Phase 1: r and z as single depth-32 chains, 2-way interleaved
                // (4-cyc chain spacing at rt2 issue). x-side folded into inits.
                __half2 r0 = __hfma2(xt2, wir2, cr2);
                __half2 z0 = __hfma2(xt2, wiz2, cz2);
                #pragma unroll
                for (int j = 0; j < 32; j++) {
                    __half2 g = u2h(H[j]);
                    r0 = __hfma2(wr[j], g, r0);
                    z0 = __hfma2(wz[j], g, z0);
                }
                // Fire both sigmoid MUFUs now; they retire under the n-chain.
                __half2 tr = htanh2(r0);
                __half2 tz = htanh2(z0);

                // Phase 2: n as 2 chains depth 16 (h-side bias in chain0).
                __half2 n0 = cnh2, n1 = zero;
                #pragma unroll
                for (int j = 0; j < 32; j += 2) {
                    n0 = __hfma2(wn[j],     u2h(H[j]),     n0);
                    n1 = __hfma2(wn[j + 1], u2h(H[j + 1]), n1);
                }
                __half2 hn2 = __hadd2(n0, n1);

                // Tail: rg/zg fixups overlap n-chain; short exposed chain only.
                __half2 rg = __hfma2(tr, hlf2, hlf2);            // sigmoid
                __half2 zg = __hfma2(tz, hlf2, hlf2);
                __half2 narg = __hfma2(rg, hn2, __hfma2(xt2, win2, cnx2));
                __half2 ng = htanh2(narg);
                h2 = __hfma2(zg, __hsub2(h2, ng), ng);  // (1-z)*n + z*h
            }
        }
    }

    // Head: out[b][o] = sum_i h_i * head_w[o][i] + head_b[o]  (fp32)
    float2 hf = __half22float2(h2);
    float ha = hf.x, hb = hf.y;
    float p0a = ha * head_w[i], p1a = ha * head_w[32 + i];
    float p0b = hb * head_w[i], p1b = hb * head_w[32 + i];
    #pragma unroll
    for (int m = 16; m > 0; m >>= 1) {
        p0a += __shfl_xor_sync(FULL_MASK, p0a, m);
        p1a += __shfl_xor_sync(FULL_MASK, p1a, m);
        p0b += __shfl_xor_sync(FULL_MASK, p0b, m);
        p1b += __shfl_xor_sync(FULL_MASK, p1b, m);
    }
    if (i == 0) {
        out[2 * b0]     = p0a + head_b[0];
        out[2 * b0 + 1] = p1a + head_b[1];
        out[2 * b0 + 2] = p0b + head_b[0];
        out[2 * b0 + 3] = p1b + head_b[1];
    }
}

extern "C" void kernel_launch(void* const* d_in, const int* in_sizes, int n_in,
                              void* d_out, int out_size) {
    const float* x      = (const float*)d_in[0];
    const float* w_ih   = (const float*)d_in[1];
    const float* w_hh   = (const float*)d_in[2];
    const float* b_ih   = (const float*)d_in[3];
    const float* b_hh   = (const float*)d_in[4];
    const float* head_w = (const float*)d_in[5];
    const float* head_b = (const float*)d_in[6];
    float* out = (float*)d_out;

    const int B = out_size / 2;           // 2048
    const int T = in_sizes[0] / B;        // 2048

    gru_kernel<<<B / 2, 32>>>(x, w_ih, w_hh, b_ih, b_hh, head_w, head_b, out, B, T);
}